// round 14
// baseline (speedup 1.0000x reference)
#include <cuda_runtime.h>
#include <math.h>

#define G 64
#define G3 262144
#define BATCH 4
#define NPTS 200000
#define NVOX (BATCH*G3)
#define NBLK1 2048           // conv1 grid size (partial-stats rows)

typedef unsigned long long ull;

// ------------------------- device scratch (no allocs allowed) -------------------------
static __device__ float    g_vox[NVOX];                    // histogram volume
static __device__ float    g_samp[NVOX];                   // grid-sampled volume
static __device__ float    g_y[(size_t)NVOX * 64];         // pre-BN conv1 output, channel-last
static __device__ unsigned g_mm[BATCH * 6];                // encoded min[3], max[3]
static __device__ ull      g_psum[NBLK1 * 32];             // per-block packed channel-pair sums
static __device__ ull      g_psq[NBLK1 * 32];              // per-block packed channel-pair sumsq
static __device__ float    g_ab[128];                      // BN affine a[64], b[64] (branch 1)
static __device__ float    g_ab2[128];                     // (branch 2)

// ------------------------- helpers -------------------------
__device__ __forceinline__ unsigned fenc(float f) {
    unsigned u = __float_as_uint(f);
    return u ^ ((unsigned)((int)u >> 31) | 0x80000000u);
}
__device__ __forceinline__ float fdec(unsigned e) {
    unsigned mask = ((int)e < 0) ? 0x80000000u : 0xFFFFFFFFu;
    return __uint_as_float(e ^ mask);
}
// div.full.f32: XLA-GPU's lowering of f32 divide (the correctness-critical op)
__device__ __forceinline__ float div_full(float a, float b) {
    float r;
    asm("div.full.f32 %0, %1, %2;" : "=f"(r) : "f"(a), "f"(b));
    return r;
}
// packed fp32x2 ops (two exact IEEE fp32 ops per instruction)
__device__ __forceinline__ void fma2(ull& d, ull a, ull b) {
    asm("fma.rn.f32x2 %0, %1, %2, %0;" : "+l"(d) : "l"(a), "l"(b));
}
__device__ __forceinline__ ull add2(ull a, ull b) {
    ull r;
    asm("add.rn.f32x2 %0, %1, %2;" : "=l"(r) : "l"(a), "l"(b));
    return r;
}
__device__ __forceinline__ ull pk(float lo, float hi) {
    ull r;
    asm("mov.b64 %0, {%1, %2};" : "=l"(r) : "f"(lo), "f"(hi));
    return r;
}
__device__ __forceinline__ float2 unpk(ull v) {
    float2 r;
    asm("mov.b64 {%0, %1}, %2;" : "=f"(r.x), "=f"(r.y) : "l"(v));
    return r;
}

// ------------------------- init -------------------------
__global__ void init_kernel() {
    int i = blockIdx.x * blockDim.x + threadIdx.x;
    int stride = gridDim.x * blockDim.x;
    for (int v = i; v < NVOX; v += stride) g_vox[v] = 0.0f;
    if (i < BATCH * 6) g_mm[i] = ((i % 6) < 3) ? 0xFFFFFFFFu : 0u;
}

// ------------------------- per-batch min/max -------------------------
__global__ void minmax_kernel(const float* __restrict__ pts) {
    int b = blockIdx.y;
    const float* p = pts + (size_t)b * NPTS * 3;
    float mn[3] = {1e30f, 1e30f, 1e30f};
    float mx[3] = {-1e30f, -1e30f, -1e30f};
    for (int i = blockIdx.x * blockDim.x + threadIdx.x; i < NPTS; i += gridDim.x * blockDim.x) {
#pragma unroll
        for (int k = 0; k < 3; k++) {
            float v = p[(size_t)i * 3 + k];
            mn[k] = fminf(mn[k], v);
            mx[k] = fmaxf(mx[k], v);
        }
    }
#pragma unroll
    for (int o = 16; o > 0; o >>= 1) {
#pragma unroll
        for (int k = 0; k < 3; k++) {
            mn[k] = fminf(mn[k], __shfl_xor_sync(0xffffffffu, mn[k], o));
            mx[k] = fmaxf(mx[k], __shfl_xor_sync(0xffffffffu, mx[k], o));
        }
    }
    if ((threadIdx.x & 31) == 0) {
#pragma unroll
        for (int k = 0; k < 3; k++) {
            atomicMin(&g_mm[b * 6 + k], fenc(mn[k]));
            atomicMax(&g_mm[b * 6 + 3 + k], fenc(mx[k]));
        }
    }
}

// ------------------------- histogram voxelization (do not touch: correctness-pinned) -------------------------
__global__ void hist_kernel(const float* __restrict__ pts) {
    int t = blockIdx.x * blockDim.x + threadIdx.x;
    if (t >= BATCH * NPTS) return;
    int b = t / NPTS;
    int i = t - b * NPTS;
    const float* p = pts + ((size_t)b * NPTS + i) * 3;
    int id[3];
#pragma unroll
    for (int k = 0; k < 3; k++) {
        float mn = fdec(g_mm[b * 6 + k]);
        float mx = fdec(g_mm[b * 6 + 3 + k]);
        float num = __fsub_rn(p[k], mn);
        float den = __fadd_rn(__fsub_rn(mx, mn), 1e-6f);
        float t0  = div_full(num, den);
        float u   = t0 * (float)G;          // exact (power-of-2 scale)
        int ii = (int)floorf(u);
        id[k] = min(max(ii, 0), G - 1);
    }
    int lin = (id[0] * G + id[1]) * G + id[2];
    atomicAdd(&g_vox[b * G3 + lin], 1.0f);
}

// ------------------------- conv3d 1->64 (SAME) + fused partial BN stats -------------------------
// channels-in-lanes: lane l owns channels {2l, 2l+1}; weights in registers (packed pairs).
__global__ __launch_bounds__(128) void conv1_kernel(int src, const float* __restrict__ wg,
                                                    const float* __restrict__ bias) {
    __shared__ float sin_s[10][10][10];
    __shared__ ull swr[2][4][32];
    const float* in = src ? g_samp : g_vox;
    int tid = threadIdx.x;
    int lane = tid & 31, w = tid >> 5;
    int b = blockIdx.z >> 3;
    int z0 = (blockIdx.z & 7) * 8;
    int y0 = blockIdx.y * 8, x0 = blockIdx.x * 8;
    const float* inb = in + (size_t)b * G3;

    for (int i = tid; i < 1000; i += 128) {
        int lz = i / 100, r = i - lz * 100, ly = r / 10, lx = r - ly * 10;
        int gz = z0 + lz - 1, gy = y0 + ly - 1, gx = x0 + lx - 1;
        float v = 0.0f;
        if ((unsigned)gz < G && (unsigned)gy < G && (unsigned)gx < G)
            v = inb[(gz * G + gy) * G + gx];
        sin_s[lz][ly][lx] = v;
    }
    ull w2[27];
#pragma unroll
    for (int t = 0; t < 27; t++)
        w2[t] = pk(wg[(2 * lane) * 27 + t], wg[(2 * lane + 1) * 27 + t]);
    ull b2 = pk(bias[2 * lane], bias[2 * lane + 1]);
    __syncthreads();

    // split stat accumulators to break RAW chains
    ull sumA = 0, sumB = 0, sqA = 0, sqB = 0;
#pragma unroll 1
    for (int zz = 0; zz < 2; zz++) {
        int z = w * 2 + zz;
#pragma unroll 1
        for (int y = 0; y < 8; y++) {
#pragma unroll
            for (int xg = 0; xg < 2; xg++) {
                ull acc2[4] = {b2, b2, b2, b2};
#pragma unroll
                for (int dz = 0; dz < 3; dz++) {
#pragma unroll
                    for (int dy = 0; dy < 3; dy++) {
                        const float* row = &sin_s[z + dz][y + dy][xg * 4];
                        ull vv[6];
#pragma unroll
                        for (int j = 0; j < 6; j++) { float v = row[j]; vv[j] = pk(v, v); }
#pragma unroll
                        for (int dx = 0; dx < 3; dx++) {
                            ull wt = w2[(dz * 3 + dy) * 3 + dx];
#pragma unroll
                            for (int vx = 0; vx < 4; vx++) fma2(acc2[vx], wt, vv[dx + vx]);
                        }
                    }
                }
                size_t vox = (size_t)(b * G3 + ((z0 + z) * G + (y0 + y)) * G + x0 + xg * 4);
#pragma unroll
                for (int vx = 0; vx < 4; vx++)
                    *(ull*)(g_y + (vox + vx) * 64 + 2 * lane) = acc2[vx];
                sumA = add2(sumA, acc2[0]);
                sumB = add2(sumB, acc2[1]);
                fma2(sqA, acc2[0], acc2[0]);
                fma2(sqB, acc2[1], acc2[1]);
                sumA = add2(sumA, acc2[2]);
                sumB = add2(sumB, acc2[3]);
                fma2(sqA, acc2[2], acc2[2]);
                fma2(sqB, acc2[3], acc2[3]);
            }
        }
    }
    swr[0][w][lane] = add2(sumA, sumB);
    swr[1][w][lane] = add2(sqA, sqB);
    __syncthreads();
    if (w == 0) {
        ull s = add2(add2(swr[0][0][lane], swr[0][1][lane]),
                     add2(swr[0][2][lane], swr[0][3][lane]));
        ull q = add2(add2(swr[1][0][lane], swr[1][1][lane]),
                     add2(swr[1][2][lane], swr[1][3][lane]));
        int bid = blockIdx.z * 64 + blockIdx.y * 8 + blockIdx.x;
        g_psum[bid * 32 + lane] = s;
        g_psq[bid * 32 + lane]  = q;
    }
}

// ------------------------- BN affine finalize: reduce conv1 partials -------------------------
__global__ void finalize_kernel(int which, const float* __restrict__ gamma,
                                const float* __restrict__ beta) {
    __shared__ double red[256][4];
    int p = blockIdx.x;   // channel pair, 0..31
    int tid = threadIdx.x;
    double s0 = 0, s1 = 0, q0 = 0, q1 = 0;
    for (int i = tid; i < NBLK1; i += 256) {
        float2 s = unpk(g_psum[i * 32 + p]);
        float2 q = unpk(g_psq[i * 32 + p]);
        s0 += s.x; s1 += s.y; q0 += q.x; q1 += q.y;
    }
    red[tid][0] = s0; red[tid][1] = s1; red[tid][2] = q0; red[tid][3] = q1;
    __syncthreads();
    for (int st = 128; st; st >>= 1) {
        if (tid < st) {
#pragma unroll
            for (int j = 0; j < 4; j++) red[tid][j] += red[tid + st][j];
        }
        __syncthreads();
    }
    if (tid == 0) {
        float* ab = which ? g_ab2 : g_ab;
        double inv = 1.0 / (double)NVOX;
#pragma unroll
        for (int h = 0; h < 2; h++) {
            int c = 2 * p + h;
            double mean = red[0][h] * inv;
            double var = red[0][2 + h] * inv - mean * mean;
            float a = gamma[c] * (float)(1.0 / sqrt(var + 1e-5));
            ab[c] = a;
            ab[64 + c] = beta[c] - (float)mean * a;
        }
    }
}

// ------------------------- conv3d 64->OC, fused BN+ReLU, tile 16x8x4, DOUBLE-BUFFERED passes -------------------------
// EPI=0: OC=3 offset conv + meshgrid + clip + trilinear border sample -> g_samp
// EPI=1: OC=1 conv + sigmoid -> outp
// block 256 threads, tile 16x8x4 (2 x-voxels/thread); 4 passes x 16 channels, 2 smem buffers.
// Pass p+1's LDGs issue BEFORE pass p's compute; BN+STS after; one barrier per pass.
// halo 18x10x6 = 1080 pos; rows padded to 5 quads (80B), swizzle q = c4 ^ ((pos>>3)&1).
template <int OC, int EPI>
__global__ __launch_bounds__(256, 1) void conv2_kernel(const float* __restrict__ wg,
                                                       const float* __restrict__ bias, int which,
                                                       float* __restrict__ outp) {
    extern __shared__ float sh[];
    float* hsbuf0 = sh;                        // 21600 floats each
    float* hsbuf1 = sh + 21600;
    float* wsbuf0 = sh + 43200;                // OC*432 floats each
    float* wsbuf1 = wsbuf0 + OC * 432;
    float* sab = wsbuf1 + OC * 432;            // 128
    const float* ab = which ? g_ab2 : g_ab;

    int tid = threadIdx.x;
    int b = blockIdx.z >> 4;
    int z0 = (blockIdx.z & 15) * 4;
    int y0 = blockIdx.y * 8, x0 = blockIdx.x * 16;
    int tx = tid & 7, ty = (tid >> 3) & 7, tz = tid >> 6;

    if (tid < 128) sab[tid] = ab[tid];
    __syncthreads();

    const float* gyb = g_y + (size_t)(b * G3) * 64;

    // ---- prologue: load pass 0 ----
    for (int i = tid; i < OC * 432; i += 256) {
        int oc = i / 432, rr = i - oc * 432, tap = rr >> 4, ic = rr & 15;
        wsbuf0[i] = wg[(oc * 64 + ic) * 27 + tap];
    }
    for (int i = tid; i < 4320; i += 256) {
        int c4 = i & 3, pos = i >> 2;
        int lz = pos / 180, rem = pos - lz * 180, ly = rem / 18, lx = rem - ly * 18;
        int gz = z0 + lz - 1, gy = y0 + ly - 1, gx = x0 + lx - 1;
        float4 v = make_float4(0.f, 0.f, 0.f, 0.f);
        if ((unsigned)gz < G && (unsigned)gy < G && (unsigned)gx < G) {
            v = *(const float4*)(gyb + ((size_t)((gz * G + gy) * G + gx)) * 64 + c4 * 4);
            float4 a4 = *(const float4*)(sab + c4 * 4);
            float4 b4 = *(const float4*)(sab + 64 + c4 * 4);
            v.x = fmaxf(fmaf(a4.x, v.x, b4.x), 0.f);
            v.y = fmaxf(fmaf(a4.y, v.y, b4.y), 0.f);
            v.z = fmaxf(fmaf(a4.z, v.z, b4.z), 0.f);
            v.w = fmaxf(fmaf(a4.w, v.w, b4.w), 0.f);
        }
        int q = c4 ^ ((pos >> 3) & 1);
        *(float4*)&hsbuf0[(size_t)(pos * 5 + q) * 4] = v;
    }
    __syncthreads();

    // half-split accumulators: [voxel][oc][packed-half]
    ull acc2[2][OC][2];
#pragma unroll
    for (int v = 0; v < 2; v++)
#pragma unroll
        for (int oc = 0; oc < OC; oc++) { acc2[v][oc][0] = 0ull; acc2[v][oc][1] = 0ull; }

    const int NV = 17;                       // ceil(4320/256)
    const int NW = (OC * 432 + 255) / 256;

#pragma unroll 1
    for (int p = 0; p < 4; p++) {
        float* hs = (p & 1) ? hsbuf1 : hsbuf0;
        float* ws = (p & 1) ? wsbuf1 : wsbuf0;

        // ---- prefetch pass p+1 into registers (issue LDGs before compute) ----
        float4 vbuf[NV];
        int    vslot[NV];
        bool   vin[NV];
        float  wbuf[NW];
        bool pref = (p < 3);
        if (pref) {
#pragma unroll
            for (int k = 0; k < NW; k++) {
                int i = tid + k * 256;
                wbuf[k] = 0.f;
                if (i < OC * 432) {
                    int oc = i / 432, rr = i - oc * 432, tap = rr >> 4, ic = rr & 15;
                    wbuf[k] = wg[(oc * 64 + (p + 1) * 16 + ic) * 27 + tap];
                }
            }
#pragma unroll
            for (int k = 0; k < NV; k++) {
                int i = tid + k * 256;
                vin[k] = false;
                vslot[k] = 0;
                if (i < 4320) {
                    int c4 = i & 3, pos = i >> 2;
                    int lz = pos / 180, rem = pos - lz * 180, ly = rem / 18, lx = rem - ly * 18;
                    int gz = z0 + lz - 1, gy = y0 + ly - 1, gx = x0 + lx - 1;
                    int q = c4 ^ ((pos >> 3) & 1);
                    vslot[k] = (pos * 5 + q) * 4;
                    if ((unsigned)gz < G && (unsigned)gy < G && (unsigned)gx < G) {
                        vin[k] = true;
                        vbuf[k] = *(const float4*)(gyb +
                                    ((size_t)((gz * G + gy) * G + gx)) * 64 + (p + 1) * 16 + c4 * 4);
                    }
                } else {
                    vslot[k] = -1;
                }
            }
        }

        // ---- compute pass p ----
#pragma unroll 1
        for (int dz = 0; dz < 3; dz++) {
#pragma unroll
            for (int dy = 0; dy < 3; dy++) {
                int rowb = ((tz + dz) * 10 + (ty + dy)) * 18 + 2 * tx;
#pragma unroll
                for (int c4 = 0; c4 < 4; c4++) {
                    ulonglong2 d[4];
#pragma unroll
                    for (int j = 0; j < 4; j++) {
                        int pos = rowb + j;
                        int q = c4 ^ ((pos >> 3) & 1);
                        d[j] = *(const ulonglong2*)(hs + (size_t)(pos * 5 + q) * 4);
                    }
                    ulonglong2 wv[3][OC];
#pragma unroll
                    for (int dx = 0; dx < 3; dx++)
#pragma unroll
                        for (int oc = 0; oc < OC; oc++)
                            wv[dx][oc] = *(const ulonglong2*)(ws + oc * 432 +
                                                              ((dz * 3 + dy) * 3 + dx) * 16 + c4 * 4);
#pragma unroll
                    for (int dx = 0; dx < 3; dx++)
#pragma unroll
                        for (int v = 0; v < 2; v++)
#pragma unroll
                            for (int oc = 0; oc < OC; oc++) {
                                fma2(acc2[v][oc][0], d[v + dx].x, wv[dx][oc].x);
                                fma2(acc2[v][oc][1], d[v + dx].y, wv[dx][oc].y);
                            }
                }
            }
        }

        // ---- BN + store prefetched pass p+1 into the other buffer ----
        if (pref) {
            float* nhs = (p & 1) ? hsbuf0 : hsbuf1;
            float* nws = (p & 1) ? wsbuf0 : wsbuf1;
#pragma unroll
            for (int k = 0; k < NW; k++) {
                int i = tid + k * 256;
                if (i < OC * 432) nws[i] = wbuf[k];
            }
#pragma unroll
            for (int k = 0; k < NV; k++) {
                if (vslot[k] >= 0) {
                    float4 v = make_float4(0.f, 0.f, 0.f, 0.f);
                    if (vin[k]) {
                        int c4 = (tid + k * 256) & 3;
                        float4 a4 = *(const float4*)(sab + (p + 1) * 16 + c4 * 4);
                        float4 b4 = *(const float4*)(sab + 64 + (p + 1) * 16 + c4 * 4);
                        v.x = fmaxf(fmaf(a4.x, vbuf[k].x, b4.x), 0.f);
                        v.y = fmaxf(fmaf(a4.y, vbuf[k].y, b4.y), 0.f);
                        v.z = fmaxf(fmaf(a4.z, vbuf[k].z, b4.z), 0.f);
                        v.w = fmaxf(fmaf(a4.w, vbuf[k].w, b4.w), 0.f);
                    }
                    *(float4*)&nhs[vslot[k]] = v;
                }
            }
        }
        __syncthreads();
    }

#pragma unroll
    for (int v = 0; v < 2; v++) {
        float accv[OC];
#pragma unroll
        for (int oc = 0; oc < OC; oc++) {
            float2 t0 = unpk(acc2[v][oc][0]);
            float2 t1 = unpk(acc2[v][oc][1]);
            accv[oc] = (t0.x + t0.y) + (t1.x + t1.y);
        }

        int d = z0 + tz, hh = y0 + ty, wxx = x0 + 2 * tx + v;
        int vlin = (d * G + hh) * G + wxx;

        if constexpr (EPI == 0) {
            const float step = 2.0f / 63.0f;
            float o0 = accv[0] + bias[0];
            float o1 = accv[1] + bias[1];
            float o2 = accv[2] + bias[2];
            float gxc = fminf(fmaxf(-1.0f + d * step + 0.1f * o0, -1.0f), 1.0f);
            float gyc = fminf(fmaxf(-1.0f + hh * step + 0.1f * o1, -1.0f), 1.0f);
            float gzc = fminf(fmaxf(-1.0f + wxx * step + 0.1f * o2, -1.0f), 1.0f);
            float ux = fminf(fmaxf(((gxc + 1.0f) * (float)G - 1.0f) * 0.5f, 0.0f), (float)(G - 1));
            float uy = fminf(fmaxf(((gyc + 1.0f) * (float)G - 1.0f) * 0.5f, 0.0f), (float)(G - 1));
            float uz = fminf(fmaxf(((gzc + 1.0f) * (float)G - 1.0f) * 0.5f, 0.0f), (float)(G - 1));
            float fx0 = floorf(ux), fy0 = floorf(uy), fz0 = floorf(uz);
            float fx = ux - fx0, fy = uy - fy0, fz = uz - fz0;
            int x0i = (int)fx0, y0i = (int)fy0, z0i = (int)fz0;
            int x1i = min(x0i + 1, G - 1), y1i = min(y0i + 1, G - 1), z1i = min(z0i + 1, G - 1);
            const float* vb = g_vox + b * G3;
            float v000 = vb[(z0i * G + y0i) * G + x0i];
            float v001 = vb[(z0i * G + y0i) * G + x1i];
            float v010 = vb[(z0i * G + y1i) * G + x0i];
            float v011 = vb[(z0i * G + y1i) * G + x1i];
            float v100 = vb[(z1i * G + y0i) * G + x0i];
            float v101 = vb[(z1i * G + y0i) * G + x1i];
            float v110 = vb[(z1i * G + y1i) * G + x0i];
            float v111 = vb[(z1i * G + y1i) * G + x1i];
            float wx0 = 1.0f - fx, wy0 = 1.0f - fy, wz0 = 1.0f - fz;
            float r = wz0 * (wy0 * (v000 * wx0 + v001 * fx) + fy * (v010 * wx0 + v011 * fx)) +
                      fz  * (wy0 * (v100 * wx0 + v101 * fx) + fy * (v110 * wx0 + v111 * fx));
            g_samp[b * G3 + vlin] = r;
        } else {
            float o = accv[0] + bias[0];
            outp[b * G3 + vlin] = 1.0f / (1.0f + expf(-o));
        }
    }
}

// ------------------------- launch -------------------------
extern "C" void kernel_launch(void* const* d_in, const int* in_sizes, int n_in,
                              void* d_out, int out_size) {
    const float* points = (const float*)d_in[0];
    const float* ow1 = (const float*)d_in[1];
    const float* ob1 = (const float*)d_in[2];
    const float* ogamma = (const float*)d_in[3];
    const float* obeta = (const float*)d_in[4];
    const float* ow2 = (const float*)d_in[5];
    const float* ob2 = (const float*)d_in[6];
    const float* dw1 = (const float*)d_in[7];
    const float* db1 = (const float*)d_in[8];
    const float* dgamma = (const float*)d_in[9];
    const float* dbeta = (const float*)d_in[10];
    const float* dw2 = (const float*)d_in[11];
    const float* db2 = (const float*)d_in[12];
    float* outp = (float*)d_out;

    static bool attr_done = false;
    if (!attr_done) {
        cudaFuncSetAttribute(conv2_kernel<3, 0>, cudaFuncAttributeMaxDynamicSharedMemorySize, 185344);
        cudaFuncSetAttribute(conv2_kernel<1, 1>, cudaFuncAttributeMaxDynamicSharedMemorySize, 178176);
        attr_done = true;
    }

    init_kernel<<<2048, 256>>>();
    minmax_kernel<<<dim3(64, BATCH), 256>>>(points);
    hist_kernel<<<(BATCH * NPTS + 255) / 256, 256>>>(points);

    // branch 1: offset conv + grid sample
    conv1_kernel<<<dim3(8, 8, BATCH * 8), 128>>>(0, ow1, ob1);
    finalize_kernel<<<32, 256>>>(0, ogamma, obeta);
    conv2_kernel<3, 0><<<dim3(4, 8, 64), 256, 183680>>>(ow2, ob2, 0, nullptr);

    // branch 2: decoder
    conv1_kernel<<<dim3(8, 8, BATCH * 8), 128>>>(1, dw1, db1);
    finalize_kernel<<<32, 256>>>(1, dgamma, dbeta);
    conv2_kernel<1, 1><<<dim3(4, 8, 64), 256, 176768>>>(dw2, db2, 1, outp);
}

// round 15
// speedup vs baseline: 1.0392x; 1.0392x over previous
#include <cuda_runtime.h>
#include <math.h>

#define G 64
#define G3 262144
#define BATCH 4
#define NPTS 200000
#define NVOX (BATCH*G3)
#define NBLK1 2048           // conv1 grid size (partial-stats rows)

typedef unsigned long long ull;

// ------------------------- device scratch (no allocs allowed) -------------------------
static __device__ float    g_vox[NVOX];                    // histogram volume
static __device__ float    g_samp[NVOX];                   // grid-sampled volume
static __device__ float    g_y[(size_t)NVOX * 64];         // pre-BN conv1 output, channel-last
static __device__ unsigned g_mm[BATCH * 6];                // encoded min[3], max[3]
static __device__ ull      g_psum[NBLK1 * 32];             // per-block packed channel-pair sums
static __device__ ull      g_psq[NBLK1 * 32];              // per-block packed channel-pair sumsq
static __device__ float    g_ab[128];                      // BN affine a[64], b[64] (branch 1)
static __device__ float    g_ab2[128];                     // (branch 2)

// ------------------------- helpers -------------------------
__device__ __forceinline__ unsigned fenc(float f) {
    unsigned u = __float_as_uint(f);
    return u ^ ((unsigned)((int)u >> 31) | 0x80000000u);
}
__device__ __forceinline__ float fdec(unsigned e) {
    unsigned mask = ((int)e < 0) ? 0x80000000u : 0xFFFFFFFFu;
    return __uint_as_float(e ^ mask);
}
// div.full.f32: XLA-GPU's lowering of f32 divide (the correctness-critical op)
__device__ __forceinline__ float div_full(float a, float b) {
    float r;
    asm("div.full.f32 %0, %1, %2;" : "=f"(r) : "f"(a), "f"(b));
    return r;
}
// packed fp32x2 ops (two exact IEEE fp32 ops per instruction)
__device__ __forceinline__ void fma2(ull& d, ull a, ull b) {
    asm("fma.rn.f32x2 %0, %1, %2, %0;" : "+l"(d) : "l"(a), "l"(b));
}
__device__ __forceinline__ ull add2(ull a, ull b) {
    ull r;
    asm("add.rn.f32x2 %0, %1, %2;" : "=l"(r) : "l"(a), "l"(b));
    return r;
}
__device__ __forceinline__ ull pk(float lo, float hi) {
    ull r;
    asm("mov.b64 %0, {%1, %2};" : "=l"(r) : "f"(lo), "f"(hi));
    return r;
}
__device__ __forceinline__ float2 unpk(ull v) {
    float2 r;
    asm("mov.b64 {%0, %1}, %2;" : "=f"(r.x), "=f"(r.y) : "l"(v));
    return r;
}

// ------------------------- init -------------------------
__global__ void init_kernel() {
    int i = blockIdx.x * blockDim.x + threadIdx.x;
    int stride = gridDim.x * blockDim.x;
    for (int v = i; v < NVOX; v += stride) g_vox[v] = 0.0f;
    if (i < BATCH * 6) g_mm[i] = ((i % 6) < 3) ? 0xFFFFFFFFu : 0u;
}

// ------------------------- per-batch min/max -------------------------
__global__ void minmax_kernel(const float* __restrict__ pts) {
    int b = blockIdx.y;
    const float* p = pts + (size_t)b * NPTS * 3;
    float mn[3] = {1e30f, 1e30f, 1e30f};
    float mx[3] = {-1e30f, -1e30f, -1e30f};
    for (int i = blockIdx.x * blockDim.x + threadIdx.x; i < NPTS; i += gridDim.x * blockDim.x) {
#pragma unroll
        for (int k = 0; k < 3; k++) {
            float v = p[(size_t)i * 3 + k];
            mn[k] = fminf(mn[k], v);
            mx[k] = fmaxf(mx[k], v);
        }
    }
#pragma unroll
    for (int o = 16; o > 0; o >>= 1) {
#pragma unroll
        for (int k = 0; k < 3; k++) {
            mn[k] = fminf(mn[k], __shfl_xor_sync(0xffffffffu, mn[k], o));
            mx[k] = fmaxf(mx[k], __shfl_xor_sync(0xffffffffu, mx[k], o));
        }
    }
    if ((threadIdx.x & 31) == 0) {
#pragma unroll
        for (int k = 0; k < 3; k++) {
            atomicMin(&g_mm[b * 6 + k], fenc(mn[k]));
            atomicMax(&g_mm[b * 6 + 3 + k], fenc(mx[k]));
        }
    }
}

// ------------------------- histogram voxelization (do not touch: correctness-pinned) -------------------------
__global__ void hist_kernel(const float* __restrict__ pts) {
    int t = blockIdx.x * blockDim.x + threadIdx.x;
    if (t >= BATCH * NPTS) return;
    int b = t / NPTS;
    int i = t - b * NPTS;
    const float* p = pts + ((size_t)b * NPTS + i) * 3;
    int id[3];
#pragma unroll
    for (int k = 0; k < 3; k++) {
        float mn = fdec(g_mm[b * 6 + k]);
        float mx = fdec(g_mm[b * 6 + 3 + k]);
        float num = __fsub_rn(p[k], mn);
        float den = __fadd_rn(__fsub_rn(mx, mn), 1e-6f);
        float t0  = div_full(num, den);
        float u   = t0 * (float)G;          // exact (power-of-2 scale)
        int ii = (int)floorf(u);
        id[k] = min(max(ii, 0), G - 1);
    }
    int lin = (id[0] * G + id[1]) * G + id[2];
    atomicAdd(&g_vox[b * G3 + lin], 1.0f);
}

// ------------------------- conv3d 1->64 (SAME) + fused partial BN stats -------------------------
// channels-in-lanes: lane l owns channels {2l, 2l+1}; weights in registers (packed pairs).
__global__ __launch_bounds__(128) void conv1_kernel(int src, const float* __restrict__ wg,
                                                    const float* __restrict__ bias) {
    __shared__ float sin_s[10][10][10];
    __shared__ ull swr[2][4][32];
    const float* in = src ? g_samp : g_vox;
    int tid = threadIdx.x;
    int lane = tid & 31, w = tid >> 5;
    int b = blockIdx.z >> 3;
    int z0 = (blockIdx.z & 7) * 8;
    int y0 = blockIdx.y * 8, x0 = blockIdx.x * 8;
    const float* inb = in + (size_t)b * G3;

    for (int i = tid; i < 1000; i += 128) {
        int lz = i / 100, r = i - lz * 100, ly = r / 10, lx = r - ly * 10;
        int gz = z0 + lz - 1, gy = y0 + ly - 1, gx = x0 + lx - 1;
        float v = 0.0f;
        if ((unsigned)gz < G && (unsigned)gy < G && (unsigned)gx < G)
            v = inb[(gz * G + gy) * G + gx];
        sin_s[lz][ly][lx] = v;
    }
    ull w2[27];
#pragma unroll
    for (int t = 0; t < 27; t++)
        w2[t] = pk(wg[(2 * lane) * 27 + t], wg[(2 * lane + 1) * 27 + t]);
    ull b2 = pk(bias[2 * lane], bias[2 * lane + 1]);
    __syncthreads();

    // split stat accumulators to break RAW chains
    ull sumA = 0, sumB = 0, sqA = 0, sqB = 0;
#pragma unroll 1
    for (int zz = 0; zz < 2; zz++) {
        int z = w * 2 + zz;
#pragma unroll 1
        for (int y = 0; y < 8; y++) {
#pragma unroll
            for (int xg = 0; xg < 2; xg++) {
                ull acc2[4] = {b2, b2, b2, b2};
#pragma unroll
                for (int dz = 0; dz < 3; dz++) {
#pragma unroll
                    for (int dy = 0; dy < 3; dy++) {
                        const float* row = &sin_s[z + dz][y + dy][xg * 4];
                        ull vv[6];
#pragma unroll
                        for (int j = 0; j < 6; j++) { float v = row[j]; vv[j] = pk(v, v); }
#pragma unroll
                        for (int dx = 0; dx < 3; dx++) {
                            ull wt = w2[(dz * 3 + dy) * 3 + dx];
#pragma unroll
                            for (int vx = 0; vx < 4; vx++) fma2(acc2[vx], wt, vv[dx + vx]);
                        }
                    }
                }
                size_t vox = (size_t)(b * G3 + ((z0 + z) * G + (y0 + y)) * G + x0 + xg * 4);
#pragma unroll
                for (int vx = 0; vx < 4; vx++)
                    *(ull*)(g_y + (vox + vx) * 64 + 2 * lane) = acc2[vx];
                sumA = add2(sumA, acc2[0]);
                sumB = add2(sumB, acc2[1]);
                fma2(sqA, acc2[0], acc2[0]);
                fma2(sqB, acc2[1], acc2[1]);
                sumA = add2(sumA, acc2[2]);
                sumB = add2(sumB, acc2[3]);
                fma2(sqA, acc2[2], acc2[2]);
                fma2(sqB, acc2[3], acc2[3]);
            }
        }
    }
    swr[0][w][lane] = add2(sumA, sumB);
    swr[1][w][lane] = add2(sqA, sqB);
    __syncthreads();
    if (w == 0) {
        ull s = add2(add2(swr[0][0][lane], swr[0][1][lane]),
                     add2(swr[0][2][lane], swr[0][3][lane]));
        ull q = add2(add2(swr[1][0][lane], swr[1][1][lane]),
                     add2(swr[1][2][lane], swr[1][3][lane]));
        int bid = blockIdx.z * 64 + blockIdx.y * 8 + blockIdx.x;
        g_psum[bid * 32 + lane] = s;
        g_psq[bid * 32 + lane]  = q;
    }
}

// ------------------------- BN affine finalize: reduce conv1 partials -------------------------
__global__ void finalize_kernel(int which, const float* __restrict__ gamma,
                                const float* __restrict__ beta) {
    __shared__ double red[256][4];
    int p = blockIdx.x;   // channel pair, 0..31
    int tid = threadIdx.x;
    double s0 = 0, s1 = 0, q0 = 0, q1 = 0;
    for (int i = tid; i < NBLK1; i += 256) {
        float2 s = unpk(g_psum[i * 32 + p]);
        float2 q = unpk(g_psq[i * 32 + p]);
        s0 += s.x; s1 += s.y; q0 += q.x; q1 += q.y;
    }
    red[tid][0] = s0; red[tid][1] = s1; red[tid][2] = q0; red[tid][3] = q1;
    __syncthreads();
    for (int st = 128; st; st >>= 1) {
        if (tid < st) {
#pragma unroll
            for (int j = 0; j < 4; j++) red[tid][j] += red[tid + st][j];
        }
        __syncthreads();
    }
    if (tid == 0) {
        float* ab = which ? g_ab2 : g_ab;
        double inv = 1.0 / (double)NVOX;
#pragma unroll
        for (int h = 0; h < 2; h++) {
            int c = 2 * p + h;
            double mean = red[0][h] * inv;
            double var = red[0][2 + h] * inv - mean * mean;
            float a = gamma[c] * (float)(1.0 / sqrt(var + 1e-5));
            ab[c] = a;
            ab[64 + c] = beta[c] - (float)mean * a;
        }
    }
}

// ------------------------- conv3d 64->OC, fused BN+ReLU, big tile 16x8x8 (R11) -------------------------
// EPI=0: OC=3 offset conv + meshgrid + clip + trilinear border sample -> g_samp
// EPI=1: OC=1 conv + sigmoid -> outp
// block 512 threads, tile 16x8x8 (2 x-voxels/thread); 4 passes x 16 channels.
// halo 18x10x10 = 1800 pos; rows padded to 5 quads (80B), swizzle q = c4 ^ ((pos>>3)&1).
// Load phase MLP-batched 4-wide; BN+ReLU only on in-volume voxels (padding stays 0).
template <int OC, int EPI>
__global__ __launch_bounds__(512) void conv2_kernel(const float* __restrict__ wg,
                                                    const float* __restrict__ bias, int which,
                                                    float* __restrict__ outp) {
    extern __shared__ float sh[];
    float* hs = sh;                    // 1800 positions * 5 quads * 4 floats = 36000 floats
    float* ws = sh + 36000;            // OC * 27 * 16
    float* sab = ws + OC * 432;        // 128
    const float* ab = which ? g_ab2 : g_ab;

    int tid = threadIdx.x;
    int b = blockIdx.z >> 3;
    int z0 = (blockIdx.z & 7) * 8;
    int y0 = blockIdx.y * 8, x0 = blockIdx.x * 16;
    int tx = tid & 7, ty = (tid >> 3) & 7, tz = tid >> 6;

    if (tid < 128) sab[tid] = ab[tid];

    // half-split accumulators: [voxel][oc][packed-half]
    ull acc2[2][OC][2];
#pragma unroll
    for (int v = 0; v < 2; v++)
#pragma unroll
        for (int oc = 0; oc < OC; oc++) { acc2[v][oc][0] = 0ull; acc2[v][oc][1] = 0ull; }

#pragma unroll 1
    for (int p = 0; p < 4; p++) {
        __syncthreads();
        for (int i = tid; i < OC * 432; i += 512) {
            int oc = i / 432, rr = i - oc * 432, tap = rr >> 4, ic = rr & 15;
            ws[i] = wg[(oc * 64 + p * 16 + ic) * 27 + tap];
        }
        // MLP-batched halo load: 7200 items (1800 pos x 4 quads), chunks of 4
#pragma unroll 1
        for (int ch = 0; ch < 4; ch++) {
            float4 vbuf[4];
            int    sslot[4];
            bool   vld[4];
#pragma unroll
            for (int k = 0; k < 4; k++) {
                int i = tid + (ch * 4 + k) * 512;
                vld[k] = (i < 7200);
                float4 v = make_float4(0.f, 0.f, 0.f, 0.f);
                int slot = 0;
                if (vld[k]) {
                    int c4 = i & 3, pos = i >> 2;
                    int lz = pos / 180, rem = pos - lz * 180, ly = rem / 18, lx = rem - ly * 18;
                    int gz = z0 + lz - 1, gy = y0 + ly - 1, gx = x0 + lx - 1;
                    if ((unsigned)gz < G && (unsigned)gy < G && (unsigned)gx < G) {
                        v = *(const float4*)(g_y +
                              ((size_t)(b * G3 + (gz * G + gy) * G + gx)) * 64 + p * 16 + c4 * 4);
                        float4 a4 = *(const float4*)(sab + p * 16 + c4 * 4);
                        float4 b4 = *(const float4*)(sab + 64 + p * 16 + c4 * 4);
                        v.x = fmaxf(fmaf(a4.x, v.x, b4.x), 0.f);
                        v.y = fmaxf(fmaf(a4.y, v.y, b4.y), 0.f);
                        v.z = fmaxf(fmaf(a4.z, v.z, b4.z), 0.f);
                        v.w = fmaxf(fmaf(a4.w, v.w, b4.w), 0.f);
                    }
                    int q = c4 ^ ((pos >> 3) & 1);
                    slot = (pos * 5 + q) * 4;
                }
                vbuf[k] = v;
                sslot[k] = slot;
            }
#pragma unroll
            for (int k = 0; k < 4; k++)
                if (vld[k]) *(float4*)&hs[sslot[k]] = vbuf[k];
        }
        __syncthreads();

#pragma unroll 1
        for (int dz = 0; dz < 3; dz++) {
#pragma unroll
            for (int dy = 0; dy < 3; dy++) {
                int rowb = ((tz + dz) * 10 + (ty + dy)) * 18 + 2 * tx;
#pragma unroll
                for (int c4 = 0; c4 < 4; c4++) {
                    ulonglong2 d[4];
#pragma unroll
                    for (int j = 0; j < 4; j++) {
                        int pos = rowb + j;
                        int q = c4 ^ ((pos >> 3) & 1);
                        d[j] = *(const ulonglong2*)(hs + (size_t)(pos * 5 + q) * 4);
                    }
                    ulonglong2 wv[3][OC];
#pragma unroll
                    for (int dx = 0; dx < 3; dx++)
#pragma unroll
                        for (int oc = 0; oc < OC; oc++)
                            wv[dx][oc] = *(const ulonglong2*)(ws + oc * 432 +
                                                              ((dz * 3 + dy) * 3 + dx) * 16 + c4 * 4);
#pragma unroll
                    for (int dx = 0; dx < 3; dx++)
#pragma unroll
                        for (int v = 0; v < 2; v++)
#pragma unroll
                            for (int oc = 0; oc < OC; oc++) {
                                fma2(acc2[v][oc][0], d[v + dx].x, wv[dx][oc].x);
                                fma2(acc2[v][oc][1], d[v + dx].y, wv[dx][oc].y);
                            }
                }
            }
        }
    }

#pragma unroll
    for (int v = 0; v < 2; v++) {
        float accv[OC];
#pragma unroll
        for (int oc = 0; oc < OC; oc++) {
            float2 t0 = unpk(acc2[v][oc][0]);
            float2 t1 = unpk(acc2[v][oc][1]);
            accv[oc] = (t0.x + t0.y) + (t1.x + t1.y);
        }

        int d = z0 + tz, hh = y0 + ty, wxx = x0 + 2 * tx + v;
        int vlin = (d * G + hh) * G + wxx;

        if constexpr (EPI == 0) {
            const float step = 2.0f / 63.0f;
            float o0 = accv[0] + bias[0];
            float o1 = accv[1] + bias[1];
            float o2 = accv[2] + bias[2];
            float gxc = fminf(fmaxf(-1.0f + d * step + 0.1f * o0, -1.0f), 1.0f);
            float gyc = fminf(fmaxf(-1.0f + hh * step + 0.1f * o1, -1.0f), 1.0f);
            float gzc = fminf(fmaxf(-1.0f + wxx * step + 0.1f * o2, -1.0f), 1.0f);
            float ux = fminf(fmaxf(((gxc + 1.0f) * (float)G - 1.0f) * 0.5f, 0.0f), (float)(G - 1));
            float uy = fminf(fmaxf(((gyc + 1.0f) * (float)G - 1.0f) * 0.5f, 0.0f), (float)(G - 1));
            float uz = fminf(fmaxf(((gzc + 1.0f) * (float)G - 1.0f) * 0.5f, 0.0f), (float)(G - 1));
            float fx0 = floorf(ux), fy0 = floorf(uy), fz0 = floorf(uz);
            float fx = ux - fx0, fy = uy - fy0, fz = uz - fz0;
            int x0i = (int)fx0, y0i = (int)fy0, z0i = (int)fz0;
            int x1i = min(x0i + 1, G - 1), y1i = min(y0i + 1, G - 1), z1i = min(z0i + 1, G - 1);
            const float* vb = g_vox + b * G3;
            float v000 = vb[(z0i * G + y0i) * G + x0i];
            float v001 = vb[(z0i * G + y0i) * G + x1i];
            float v010 = vb[(z0i * G + y1i) * G + x0i];
            float v011 = vb[(z0i * G + y1i) * G + x1i];
            float v100 = vb[(z1i * G + y0i) * G + x0i];
            float v101 = vb[(z1i * G + y0i) * G + x1i];
            float v110 = vb[(z1i * G + y1i) * G + x0i];
            float v111 = vb[(z1i * G + y1i) * G + x1i];
            float wx0 = 1.0f - fx, wy0 = 1.0f - fy, wz0 = 1.0f - fz;
            float r = wz0 * (wy0 * (v000 * wx0 + v001 * fx) + fy * (v010 * wx0 + v011 * fx)) +
                      fz  * (wy0 * (v100 * wx0 + v101 * fx) + fy * (v110 * wx0 + v111 * fx));
            g_samp[b * G3 + vlin] = r;
        } else {
            float o = accv[0] + bias[0];
            outp[b * G3 + vlin] = 1.0f / (1.0f + expf(-o));
        }
    }
}

// ------------------------- launch -------------------------
extern "C" void kernel_launch(void* const* d_in, const int* in_sizes, int n_in,
                              void* d_out, int out_size) {
    const float* points = (const float*)d_in[0];
    const float* ow1 = (const float*)d_in[1];
    const float* ob1 = (const float*)d_in[2];
    const float* ogamma = (const float*)d_in[3];
    const float* obeta = (const float*)d_in[4];
    const float* ow2 = (const float*)d_in[5];
    const float* ob2 = (const float*)d_in[6];
    const float* dw1 = (const float*)d_in[7];
    const float* db1 = (const float*)d_in[8];
    const float* dgamma = (const float*)d_in[9];
    const float* dbeta = (const float*)d_in[10];
    const float* dw2 = (const float*)d_in[11];
    const float* db2 = (const float*)d_in[12];
    float* outp = (float*)d_out;

    static bool attr_done = false;
    if (!attr_done) {
        cudaFuncSetAttribute(conv2_kernel<3, 0>, cudaFuncAttributeMaxDynamicSharedMemorySize, 151552);
        cudaFuncSetAttribute(conv2_kernel<1, 1>, cudaFuncAttributeMaxDynamicSharedMemorySize, 148480);
        attr_done = true;
    }

    init_kernel<<<2048, 256>>>();
    minmax_kernel<<<dim3(64, BATCH), 256>>>(points);
    hist_kernel<<<(BATCH * NPTS + 255) / 256, 256>>>(points);

    // branch 1: offset conv + grid sample
    conv1_kernel<<<dim3(8, 8, BATCH * 8), 128>>>(0, ow1, ob1);
    finalize_kernel<<<32, 256>>>(0, ogamma, obeta);
    conv2_kernel<3, 0><<<dim3(4, 8, 32), 512, 149696>>>(ow2, ob2, 0, nullptr);

    // branch 2: decoder
    conv1_kernel<<<dim3(8, 8, BATCH * 8), 128>>>(1, dw1, db1);
    finalize_kernel<<<32, 256>>>(1, dgamma, dbeta);
    conv2_kernel<1, 1><<<dim3(4, 8, 32), 512, 146240>>>(dw2, db2, 1, outp);
}

// round 16
// speedup vs baseline: 1.1774x; 1.1330x over previous
#include <cuda_runtime.h>
#include <math.h>

#define G 64
#define G3 262144
#define BATCH 4
#define NPTS 200000
#define NVOX (BATCH*G3)
#define NBLK1 2048           // conv1 grid size (partial-stats rows)

typedef unsigned long long ull;

// ------------------------- device scratch (no allocs allowed) -------------------------
static __device__ float    g_vox[NVOX];                    // histogram volume
static __device__ float    g_samp[NVOX];                   // grid-sampled volume
static __device__ float    g_y[(size_t)NVOX * 64];         // pre-BN conv1 output, channel-last
static __device__ unsigned g_mm[BATCH * 6];                // encoded min[3], max[3]
static __device__ ull      g_psum[NBLK1 * 32];             // per-block packed channel-pair sums
static __device__ ull      g_psq[NBLK1 * 32];              // per-block packed channel-pair sumsq
static __device__ float    g_ab[128];                      // BN affine a[64], b[64] (branch 1)
static __device__ float    g_ab2[128];                     // (branch 2)

// ------------------------- helpers -------------------------
__device__ __forceinline__ unsigned fenc(float f) {
    unsigned u = __float_as_uint(f);
    return u ^ ((unsigned)((int)u >> 31) | 0x80000000u);
}
__device__ __forceinline__ float fdec(unsigned e) {
    unsigned mask = ((int)e < 0) ? 0x80000000u : 0xFFFFFFFFu;
    return __uint_as_float(e ^ mask);
}
// div.full.f32: XLA-GPU's lowering of f32 divide (the correctness-critical op)
__device__ __forceinline__ float div_full(float a, float b) {
    float r;
    asm("div.full.f32 %0, %1, %2;" : "=f"(r) : "f"(a), "f"(b));
    return r;
}
// packed fp32x2 ops (two exact IEEE fp32 ops per instruction)
__device__ __forceinline__ void fma2(ull& d, ull a, ull b) {
    asm("fma.rn.f32x2 %0, %1, %2, %0;" : "+l"(d) : "l"(a), "l"(b));
}
__device__ __forceinline__ ull add2(ull a, ull b) {
    ull r;
    asm("add.rn.f32x2 %0, %1, %2;" : "=l"(r) : "l"(a), "l"(b));
    return r;
}
__device__ __forceinline__ ull pk(float lo, float hi) {
    ull r;
    asm("mov.b64 %0, {%1, %2};" : "=l"(r) : "f"(lo), "f"(hi));
    return r;
}
__device__ __forceinline__ float2 unpk(ull v) {
    float2 r;
    asm("mov.b64 {%0, %1}, %2;" : "=f"(r.x), "=f"(r.y) : "l"(v));
    return r;
}

// ------------------------- init -------------------------
__global__ void init_kernel() {
    int i = blockIdx.x * blockDim.x + threadIdx.x;
    int stride = gridDim.x * blockDim.x;
    for (int v = i; v < NVOX; v += stride) g_vox[v] = 0.0f;
    if (i < BATCH * 6) g_mm[i] = ((i % 6) < 3) ? 0xFFFFFFFFu : 0u;
}

// ------------------------- per-batch min/max -------------------------
__global__ void minmax_kernel(const float* __restrict__ pts) {
    int b = blockIdx.y;
    const float* p = pts + (size_t)b * NPTS * 3;
    float mn[3] = {1e30f, 1e30f, 1e30f};
    float mx[3] = {-1e30f, -1e30f, -1e30f};
    for (int i = blockIdx.x * blockDim.x + threadIdx.x; i < NPTS; i += gridDim.x * blockDim.x) {
#pragma unroll
        for (int k = 0; k < 3; k++) {
            float v = p[(size_t)i * 3 + k];
            mn[k] = fminf(mn[k], v);
            mx[k] = fmaxf(mx[k], v);
        }
    }
#pragma unroll
    for (int o = 16; o > 0; o >>= 1) {
#pragma unroll
        for (int k = 0; k < 3; k++) {
            mn[k] = fminf(mn[k], __shfl_xor_sync(0xffffffffu, mn[k], o));
            mx[k] = fmaxf(mx[k], __shfl_xor_sync(0xffffffffu, mx[k], o));
        }
    }
    if ((threadIdx.x & 31) == 0) {
#pragma unroll
        for (int k = 0; k < 3; k++) {
            atomicMin(&g_mm[b * 6 + k], fenc(mn[k]));
            atomicMax(&g_mm[b * 6 + 3 + k], fenc(mx[k]));
        }
    }
}

// ------------------------- histogram voxelization (do not touch: correctness-pinned) -------------------------
__global__ void hist_kernel(const float* __restrict__ pts) {
    int t = blockIdx.x * blockDim.x + threadIdx.x;
    if (t >= BATCH * NPTS) return;
    int b = t / NPTS;
    int i = t - b * NPTS;
    const float* p = pts + ((size_t)b * NPTS + i) * 3;
    int id[3];
#pragma unroll
    for (int k = 0; k < 3; k++) {
        float mn = fdec(g_mm[b * 6 + k]);
        float mx = fdec(g_mm[b * 6 + 3 + k]);
        float num = __fsub_rn(p[k], mn);
        float den = __fadd_rn(__fsub_rn(mx, mn), 1e-6f);
        float t0  = div_full(num, den);
        float u   = t0 * (float)G;          // exact (power-of-2 scale)
        int ii = (int)floorf(u);
        id[k] = min(max(ii, 0), G - 1);
    }
    int lin = (id[0] * G + id[1]) * G + id[2];
    atomicAdd(&g_vox[b * G3 + lin], 1.0f);
}

// ------------------------- conv3d 1->64 (SAME) + fused partial BN stats -------------------------
// channels-in-lanes: lane l owns channels {2l, 2l+1}; weights in registers (packed pairs).
__global__ __launch_bounds__(128) void conv1_kernel(int src, const float* __restrict__ wg,
                                                    const float* __restrict__ bias) {
    __shared__ float sin_s[10][10][10];
    __shared__ ull swr[2][4][32];
    const float* in = src ? g_samp : g_vox;
    int tid = threadIdx.x;
    int lane = tid & 31, w = tid >> 5;
    int b = blockIdx.z >> 3;
    int z0 = (blockIdx.z & 7) * 8;
    int y0 = blockIdx.y * 8, x0 = blockIdx.x * 8;
    const float* inb = in + (size_t)b * G3;

    for (int i = tid; i < 1000; i += 128) {
        int lz = i / 100, r = i - lz * 100, ly = r / 10, lx = r - ly * 10;
        int gz = z0 + lz - 1, gy = y0 + ly - 1, gx = x0 + lx - 1;
        float v = 0.0f;
        if ((unsigned)gz < G && (unsigned)gy < G && (unsigned)gx < G)
            v = inb[(gz * G + gy) * G + gx];
        sin_s[lz][ly][lx] = v;
    }
    ull w2[27];
#pragma unroll
    for (int t = 0; t < 27; t++)
        w2[t] = pk(wg[(2 * lane) * 27 + t], wg[(2 * lane + 1) * 27 + t]);
    ull b2 = pk(bias[2 * lane], bias[2 * lane + 1]);
    __syncthreads();

    // split stat accumulators to break RAW chains
    ull sumA = 0, sumB = 0, sqA = 0, sqB = 0;
#pragma unroll 1
    for (int zz = 0; zz < 2; zz++) {
        int z = w * 2 + zz;
#pragma unroll 1
        for (int y = 0; y < 8; y++) {
#pragma unroll
            for (int xg = 0; xg < 2; xg++) {
                ull acc2[4] = {b2, b2, b2, b2};
#pragma unroll
                for (int dz = 0; dz < 3; dz++) {
#pragma unroll
                    for (int dy = 0; dy < 3; dy++) {
                        const float* row = &sin_s[z + dz][y + dy][xg * 4];
                        ull vv[6];
#pragma unroll
                        for (int j = 0; j < 6; j++) { float v = row[j]; vv[j] = pk(v, v); }
#pragma unroll
                        for (int dx = 0; dx < 3; dx++) {
                            ull wt = w2[(dz * 3 + dy) * 3 + dx];
#pragma unroll
                            for (int vx = 0; vx < 4; vx++) fma2(acc2[vx], wt, vv[dx + vx]);
                        }
                    }
                }
                size_t vox = (size_t)(b * G3 + ((z0 + z) * G + (y0 + y)) * G + x0 + xg * 4);
#pragma unroll
                for (int vx = 0; vx < 4; vx++)
                    *(ull*)(g_y + (vox + vx) * 64 + 2 * lane) = acc2[vx];
                sumA = add2(sumA, acc2[0]);
                sumB = add2(sumB, acc2[1]);
                fma2(sqA, acc2[0], acc2[0]);
                fma2(sqB, acc2[1], acc2[1]);
                sumA = add2(sumA, acc2[2]);
                sumB = add2(sumB, acc2[3]);
                fma2(sqA, acc2[2], acc2[2]);
                fma2(sqB, acc2[3], acc2[3]);
            }
        }
    }
    swr[0][w][lane] = add2(sumA, sumB);
    swr[1][w][lane] = add2(sqA, sqB);
    __syncthreads();
    if (w == 0) {
        ull s = add2(add2(swr[0][0][lane], swr[0][1][lane]),
                     add2(swr[0][2][lane], swr[0][3][lane]));
        ull q = add2(add2(swr[1][0][lane], swr[1][1][lane]),
                     add2(swr[1][2][lane], swr[1][3][lane]));
        int bid = blockIdx.z * 64 + blockIdx.y * 8 + blockIdx.x;
        g_psum[bid * 32 + lane] = s;
        g_psq[bid * 32 + lane]  = q;
    }
}

// ------------------------- BN affine finalize: reduce conv1 partials -------------------------
__global__ void finalize_kernel(int which, const float* __restrict__ gamma,
                                const float* __restrict__ beta) {
    __shared__ double red[256][4];
    int p = blockIdx.x;   // channel pair, 0..31
    int tid = threadIdx.x;
    double s0 = 0, s1 = 0, q0 = 0, q1 = 0;
    for (int i = tid; i < NBLK1; i += 256) {
        float2 s = unpk(g_psum[i * 32 + p]);
        float2 q = unpk(g_psq[i * 32 + p]);
        s0 += s.x; s1 += s.y; q0 += q.x; q1 += q.y;
    }
    red[tid][0] = s0; red[tid][1] = s1; red[tid][2] = q0; red[tid][3] = q1;
    __syncthreads();
    for (int st = 128; st; st >>= 1) {
        if (tid < st) {
#pragma unroll
            for (int j = 0; j < 4; j++) red[tid][j] += red[tid + st][j];
        }
        __syncthreads();
    }
    if (tid == 0) {
        float* ab = which ? g_ab2 : g_ab;
        double inv = 1.0 / (double)NVOX;
#pragma unroll
        for (int h = 0; h < 2; h++) {
            int c = 2 * p + h;
            double mean = red[0][h] * inv;
            double var = red[0][2 + h] * inv - mean * mean;
            float a = gamma[c] * (float)(1.0 / sqrt(var + 1e-5));
            ab[c] = a;
            ab[64 + c] = beta[c] - (float)mean * a;
        }
    }
}

// ------------------------- conv3d 64->OC, fused BN+ReLU, big tile 16x8x8 (bit-exact R11) -------------------------
// EPI=0: OC=3 offset conv + meshgrid + clip + trilinear border sample -> g_samp
// EPI=1: OC=1 conv + sigmoid -> outp
// block 512 threads, tile 16x8x8 (2 x-voxels/thread); 4 passes x 16 channels.
// halo 18x10x10 = 1800 pos; rows padded to 5 quads (80B), swizzle q = c4 ^ ((pos>>3)&1).
template <int OC, int EPI>
__global__ __launch_bounds__(512) void conv2_kernel(const float* __restrict__ wg,
                                                    const float* __restrict__ bias, int which,
                                                    float* __restrict__ outp) {
    extern __shared__ float sh[];
    float* hs = sh;                    // 1800 positions * 5 quads * 4 floats = 36000 floats
    float* ws = sh + 36000;            // OC * 27 * 16
    float* sab = ws + OC * 432;        // 128
    const float* ab = which ? g_ab2 : g_ab;

    int tid = threadIdx.x;
    int b = blockIdx.z >> 3;
    int z0 = (blockIdx.z & 7) * 8;
    int y0 = blockIdx.y * 8, x0 = blockIdx.x * 16;
    int tx = tid & 7, ty = (tid >> 3) & 7, tz = tid >> 6;

    if (tid < 128) sab[tid] = ab[tid];

    // half-split accumulators: [voxel][oc][packed-half]
    ull acc2[2][OC][2];
#pragma unroll
    for (int v = 0; v < 2; v++)
#pragma unroll
        for (int oc = 0; oc < OC; oc++) { acc2[v][oc][0] = 0ull; acc2[v][oc][1] = 0ull; }

#pragma unroll 1
    for (int p = 0; p < 4; p++) {
        __syncthreads();
        for (int i = tid; i < OC * 432; i += 512) {
            int oc = i / 432, rr = i - oc * 432, tap = rr >> 4, ic = rr & 15;
            ws[i] = wg[(oc * 64 + p * 16 + ic) * 27 + tap];
        }
        for (int i = tid; i < 7200; i += 512) {
            int c4 = i & 3, pos = i >> 2;
            int lz = pos / 180, rem = pos - lz * 180, ly = rem / 18, lx = rem - ly * 18;
            int gz = z0 + lz - 1, gy = y0 + ly - 1, gx = x0 + lx - 1;
            float4 v = make_float4(0.f, 0.f, 0.f, 0.f);
            if ((unsigned)gz < G && (unsigned)gy < G && (unsigned)gx < G) {
                float4 yv = *(const float4*)(g_y + ((size_t)(b * G3 + (gz * G + gy) * G + gx)) * 64 +
                                             p * 16 + c4 * 4);
                float4 a4 = *(const float4*)(sab + p * 16 + c4 * 4);
                float4 b4 = *(const float4*)(sab + 64 + p * 16 + c4 * 4);
                v.x = fmaxf(fmaf(a4.x, yv.x, b4.x), 0.f);
                v.y = fmaxf(fmaf(a4.y, yv.y, b4.y), 0.f);
                v.z = fmaxf(fmaf(a4.z, yv.z, b4.z), 0.f);
                v.w = fmaxf(fmaf(a4.w, yv.w, b4.w), 0.f);
            }
            int q = c4 ^ ((pos >> 3) & 1);
            *(float4*)&hs[(size_t)(pos * 5 + q) * 4] = v;
        }
        __syncthreads();

#pragma unroll 1
        for (int dz = 0; dz < 3; dz++) {
#pragma unroll
            for (int dy = 0; dy < 3; dy++) {
                int rowb = ((tz + dz) * 10 + (ty + dy)) * 18 + 2 * tx;
#pragma unroll
                for (int c4 = 0; c4 < 4; c4++) {
                    ulonglong2 d[4];
#pragma unroll
                    for (int j = 0; j < 4; j++) {
                        int pos = rowb + j;
                        int q = c4 ^ ((pos >> 3) & 1);
                        d[j] = *(const ulonglong2*)(hs + (size_t)(pos * 5 + q) * 4);
                    }
                    ulonglong2 wv[3][OC];
#pragma unroll
                    for (int dx = 0; dx < 3; dx++)
#pragma unroll
                        for (int oc = 0; oc < OC; oc++)
                            wv[dx][oc] = *(const ulonglong2*)(ws + oc * 432 +
                                                              ((dz * 3 + dy) * 3 + dx) * 16 + c4 * 4);
#pragma unroll
                    for (int dx = 0; dx < 3; dx++)
#pragma unroll
                        for (int v = 0; v < 2; v++)
#pragma unroll
                            for (int oc = 0; oc < OC; oc++) {
                                fma2(acc2[v][oc][0], d[v + dx].x, wv[dx][oc].x);
                                fma2(acc2[v][oc][1], d[v + dx].y, wv[dx][oc].y);
                            }
                }
            }
        }
    }

#pragma unroll
    for (int v = 0; v < 2; v++) {
        float accv[OC];
#pragma unroll
        for (int oc = 0; oc < OC; oc++) {
            float2 t0 = unpk(acc2[v][oc][0]);
            float2 t1 = unpk(acc2[v][oc][1]);
            accv[oc] = (t0.x + t0.y) + (t1.x + t1.y);
        }

        int d = z0 + tz, hh = y0 + ty, wxx = x0 + 2 * tx + v;
        int vlin = (d * G + hh) * G + wxx;

        if constexpr (EPI == 0) {
            const float step = 2.0f / 63.0f;
            float o0 = accv[0] + bias[0];
            float o1 = accv[1] + bias[1];
            float o2 = accv[2] + bias[2];
            float gxc = fminf(fmaxf(-1.0f + d * step + 0.1f * o0, -1.0f), 1.0f);
            float gyc = fminf(fmaxf(-1.0f + hh * step + 0.1f * o1, -1.0f), 1.0f);
            float gzc = fminf(fmaxf(-1.0f + wxx * step + 0.1f * o2, -1.0f), 1.0f);
            float ux = fminf(fmaxf(((gxc + 1.0f) * (float)G - 1.0f) * 0.5f, 0.0f), (float)(G - 1));
            float uy = fminf(fmaxf(((gyc + 1.0f) * (float)G - 1.0f) * 0.5f, 0.0f), (float)(G - 1));
            float uz = fminf(fmaxf(((gzc + 1.0f) * (float)G - 1.0f) * 0.5f, 0.0f), (float)(G - 1));
            float fx0 = floorf(ux), fy0 = floorf(uy), fz0 = floorf(uz);
            float fx = ux - fx0, fy = uy - fy0, fz = uz - fz0;
            int x0i = (int)fx0, y0i = (int)fy0, z0i = (int)fz0;
            int x1i = min(x0i + 1, G - 1), y1i = min(y0i + 1, G - 1), z1i = min(z0i + 1, G - 1);
            const float* vb = g_vox + b * G3;
            float v000 = vb[(z0i * G + y0i) * G + x0i];
            float v001 = vb[(z0i * G + y0i) * G + x1i];
            float v010 = vb[(z0i * G + y1i) * G + x0i];
            float v011 = vb[(z0i * G + y1i) * G + x1i];
            float v100 = vb[(z1i * G + y0i) * G + x0i];
            float v101 = vb[(z1i * G + y0i) * G + x1i];
            float v110 = vb[(z1i * G + y1i) * G + x0i];
            float v111 = vb[(z1i * G + y1i) * G + x1i];
            float wx0 = 1.0f - fx, wy0 = 1.0f - fy, wz0 = 1.0f - fz;
            float r = wz0 * (wy0 * (v000 * wx0 + v001 * fx) + fy * (v010 * wx0 + v011 * fx)) +
                      fz  * (wy0 * (v100 * wx0 + v101 * fx) + fy * (v110 * wx0 + v111 * fx));
            g_samp[b * G3 + vlin] = r;
        } else {
            float o = accv[0] + bias[0];
            outp[b * G3 + vlin] = 1.0f / (1.0f + expf(-o));
        }
    }
}

// ------------------------- launch -------------------------
extern "C" void kernel_launch(void* const* d_in, const int* in_sizes, int n_in,
                              void* d_out, int out_size) {
    const float* points = (const float*)d_in[0];
    const float* ow1 = (const float*)d_in[1];
    const float* ob1 = (const float*)d_in[2];
    const float* ogamma = (const float*)d_in[3];
    const float* obeta = (const float*)d_in[4];
    const float* ow2 = (const float*)d_in[5];
    const float* ob2 = (const float*)d_in[6];
    const float* dw1 = (const float*)d_in[7];
    const float* db1 = (const float*)d_in[8];
    const float* dgamma = (const float*)d_in[9];
    const float* dbeta = (const float*)d_in[10];
    const float* dw2 = (const float*)d_in[11];
    const float* db2 = (const float*)d_in[12];
    float* outp = (float*)d_out;

    static bool attr_done = false;
    if (!attr_done) {
        cudaFuncSetAttribute(conv2_kernel<3, 0>, cudaFuncAttributeMaxDynamicSharedMemorySize, 151552);
        cudaFuncSetAttribute(conv2_kernel<1, 1>, cudaFuncAttributeMaxDynamicSharedMemorySize, 148480);
        attr_done = true;
    }

    init_kernel<<<2048, 256>>>();
    minmax_kernel<<<dim3(64, BATCH), 256>>>(points);
    hist_kernel<<<(BATCH * NPTS + 255) / 256, 256>>>(points);

    // branch 1: offset conv + grid sample
    conv1_kernel<<<dim3(8, 8, BATCH * 8), 128>>>(0, ow1, ob1);
    finalize_kernel<<<32, 256>>>(0, ogamma, obeta);
    conv2_kernel<3, 0><<<dim3(4, 8, 32), 512, 149696>>>(ow2, ob2, 0, nullptr);

    // branch 2: decoder
    conv1_kernel<<<dim3(8, 8, BATCH * 8), 128>>>(1, dw1, db1);
    finalize_kernel<<<32, 256>>>(1, dgamma, dbeta);
    conv2_kernel<1, 1><<<dim3(4, 8, 32), 512, 146240>>>(dw2, db2, 1, outp);
}